// round 4
// baseline (speedup 1.0000x reference)
#include <cuda_runtime.h>
#include <stdint.h>

#define BN_EPS 1e-5f

namespace {
constexpr int Nn = 64, C = 256, H = 56, W = 56;
constexpr int PW = 58;          // padded linear row width
constexpr int PIX = 3520;       // padded pixel slots per image (>= 3446 reach)
constexpr int MVALID = 56 * PW; // 3248 linear output positions
constexpr int MTILES = 26;      // 26*128 = 3328 >= 3248
constexpr int CHUNKS = 72;      // 9 taps * 8 ci-chunks of 32
constexpr int NSPLIT = 2;       // co halves of 128

// dynamic smem layout (bytes from 256-aligned base)
constexpr int STAGE_SZ = 8192;  // A 4KB + B 4KB
constexpr int PIPE_BYTES = 4 * STAGE_SZ;       // 32768
constexpr int STG2_WSTR = 4352;                 // per-warp f32 [16co][68p]
constexpr int MAIN_SZ = 34816;                  // max(pipe, 8*4352)
constexpr int SC_OFF = MAIN_SZ, SH_OFF = MAIN_SZ + 512;
constexpr int DYN = MAIN_SZ + 1024 + 256;       // + bn + align slack
constexpr int STG1_STR = 144;                   // int8 row stride (16B-mult, bank-spread)
}

__device__ int8_t g_act1[(size_t)Nn * PIX * C];
__device__ int8_t g_act2[(size_t)Nn * PIX * C];
__device__ int8_t g_w1[9 * C * C];
__device__ int8_t g_w2[9 * C * C];

// ---------------- helpers ----------------
__device__ __forceinline__ uint32_t smem_u32(const void* p) {
    uint32_t a;
    asm("{ .reg .u64 t; cvta.to.shared.u64 t, %1; cvt.u32.u64 %0, t; }" : "=r"(a) : "l"(p));
    return a;
}
__device__ __forceinline__ void cpa16(uint32_t s, const void* g) {
    asm volatile("cp.async.cg.shared.global [%0], [%1], 16;" ::"r"(s), "l"(g));
}
__device__ __forceinline__ void cpa_commit() { asm volatile("cp.async.commit_group;"); }
template <int N>
__device__ __forceinline__ void cpa_wait() {
    asm volatile("cp.async.wait_group %0;" ::"n"(N) : "memory");
}
__device__ __forceinline__ void ldmx4(uint32_t& r0, uint32_t& r1, uint32_t& r2, uint32_t& r3,
                                      uint32_t addr) {
    asm volatile("ldmatrix.sync.aligned.m8n8.x4.shared.b16 {%0,%1,%2,%3}, [%4];"
                 : "=r"(r0), "=r"(r1), "=r"(r2), "=r"(r3) : "r"(addr));
}
__device__ __forceinline__ void imma(int* d, uint32_t a0, uint32_t a1, uint32_t a2, uint32_t a3,
                                     uint32_t b0, uint32_t b1) {
    asm volatile(
        "mma.sync.aligned.m16n8k32.row.col.s32.s8.s8.s32 "
        "{%0,%1,%2,%3}, {%4,%5,%6,%7}, {%8,%9}, {%0,%1,%2,%3};"
        : "+r"(d[0]), "+r"(d[1]), "+r"(d[2]), "+r"(d[3])
        : "r"(a0), "r"(a1), "r"(a2), "r"(a3), "r"(b0), "r"(b1));
}
__device__ __forceinline__ uint32_t sgn8(float v) {
    return (uint32_t)(uint8_t)(int8_t)((v > 0.f) - (v < 0.f));
}

// ---------------- prep kernels ----------------
__global__ void k_zero() {
    size_t tot = ((size_t)Nn * PIX * C) / 16;
    size_t stride = (size_t)gridDim.x * blockDim.x;
    uint4 z = {0u, 0u, 0u, 0u};
    for (size_t i = blockIdx.x * (size_t)blockDim.x + threadIdx.x; i < tot; i += stride) {
        ((uint4*)g_act1)[i] = z;
        ((uint4*)g_act2)[i] = z;
    }
}

__global__ void k_pack_x(const float* __restrict__ x) {
    __shared__ __align__(16) int8_t t[W * C];  // [w][c]
    const int hh = blockIdx.x, n = blockIdx.y, tid = threadIdx.x;
    for (int i = tid; i < C * W; i += 256) {
        int c = i / W, w = i - c * W;
        float v = x[(((size_t)n * C + c) * H + hh) * W + w];
        t[w * C + c] = (int8_t)((v > 0.f) - (v < 0.f));
    }
    __syncthreads();
    for (int i = tid; i < W * (C / 16); i += 256) {
        int w = i >> 4, q = i & 15;
        uint4 val = ((const uint4*)(t + w * C))[q];
        size_t o = ((size_t)n * PIX + (size_t)(hh + 1) * PW + (w + 1)) * C + q * 16;
        *(uint4*)(g_act1 + o) = val;
    }
}

__global__ void k_pack_w(const float* __restrict__ wsrc, int which) {
    int8_t* dst = which ? g_w2 : g_w1;
    const int co = blockIdx.x, ci = threadIdx.x;
#pragma unroll
    for (int tap = 0; tap < 9; tap++) {
        float v = wsrc[((size_t)co * C + ci) * 9 + tap];
        dst[((size_t)tap * C + co) * C + ci] = (int8_t)((v > 0.f) - (v < 0.f));
    }
}

// ---------------- implicit-GEMM conv (int8 mma.sync, exact) ----------------
template <int STAGE>
__global__ void __launch_bounds__(256, 2) k_conv(
    const float* __restrict__ bg, const float* __restrict__ bb,
    const float* __restrict__ bm, const float* __restrict__ bv,
    const float* __restrict__ xres, float* __restrict__ out) {
    extern __shared__ char dsm[];
    const uint32_t raw = smem_u32(dsm);
    const uint32_t base = (raw + 255u) & ~255u;
    char* sb = dsm + (base - raw);
    float* scs = (float*)(sb + SC_OFF);
    float* shs = (float*)(sb + SH_OFF);

    const int tid = threadIdx.x, lane = tid & 31, wid = tid >> 5;
    const int warpM = wid & 1, warpN = wid >> 1;
    const int m0 = blockIdx.x * 128;
    const int nhalf = blockIdx.y;
    const int n = blockIdx.z;
    const int8_t* __restrict__ src = (STAGE == 1) ? g_act1 : g_act2;
    const int8_t* __restrict__ wsrc = (STAGE == 1) ? g_w1 : g_w2;

    if (tid < 128) {
        int co = nhalf * 128 + tid;
        float sc = bg[co] * rsqrtf(bv[co] + BN_EPS);
        scs[tid] = sc;
        shs[tid] = bb[co] - bm[co] * sc;
    }

    // cp.async one chunk (tap, ci32) into pipeline stage s
    auto load_chunk = [&](int c, int s) {
        const int tap = c >> 3, cc = c & 7;
        const int shift = (tap / 3) * PW + (tap % 3);
        const int8_t* ag = src + ((size_t)n * PIX + m0 + shift) * C + cc * 32 +
                           (tid >> 1) * C + (tid & 1) * 16;
        const int8_t* bgp = wsrc + ((size_t)tap * C + nhalf * 128) * C + cc * 32 +
                            (tid >> 1) * C + (tid & 1) * 16;
        uint32_t so = base + s * STAGE_SZ + (tid >> 1) * 32 +
                      (((tid & 1) ^ ((tid >> 3) & 1)) << 4);
        cpa16(so, ag);
        cpa16(so + 4096, bgp);
        cpa_commit();
    };

    int d[4][4][4];
#pragma unroll
    for (int mi = 0; mi < 4; mi++)
#pragma unroll
        for (int ni = 0; ni < 4; ni++)
#pragma unroll
            for (int k = 0; k < 4; k++) d[mi][ni][k] = 0;

    load_chunk(0, 0);
    load_chunk(1, 1);
    load_chunk(2, 2);

    for (int i = 0; i < CHUNKS; i++) {
        cpa_wait<2>();
        __syncthreads();
        if (i + 3 < CHUNKS) load_chunk(i + 3, (i + 3) & 3);
        else cpa_commit();  // keep group accounting uniform

        const uint32_t aoff = base + (i & 3) * STAGE_SZ;
        const uint32_t boff = aoff + 4096;

        uint32_t b[4][2];
#pragma unroll
        for (int j = 0; j < 2; j++) {
            int rowB = warpN * 32 + j * 16 + ((lane >> 4) & 1) * 8 + (lane & 7);
            int kh = (lane >> 3) & 1;
            uint32_t ad = boff + rowB * 32 + ((kh ^ ((rowB >> 2) & 1)) << 4);
            uint32_t r0, r1, r2, r3;
            ldmx4(r0, r1, r2, r3, ad);
            b[2 * j][0] = r0; b[2 * j][1] = r1;
            b[2 * j + 1][0] = r2; b[2 * j + 1][1] = r3;
        }
#pragma unroll
        for (int mi = 0; mi < 4; mi++) {
            int rowA = warpM * 64 + mi * 16 + (lane & 15);
            int kh = lane >> 4;
            uint32_t ad = aoff + rowA * 32 + ((kh ^ ((rowA >> 2) & 1)) << 4);
            uint32_t a0, a1, a2, a3;
            ldmx4(a0, a1, a2, a3, ad);
#pragma unroll
            for (int ni = 0; ni < 4; ni++)
                imma(d[mi][ni], a0, a1, a2, a3, b[ni][0], b[ni][1]);
        }
    }
    __syncthreads();  // pipeline smem now reusable for epilogue staging

    if (STAGE == 1) {
        // BN + sign -> int8, stage [128p][128co] then vector-store to g_act2
        uint8_t* stg = (uint8_t*)sb;
#pragma unroll
        for (int mi = 0; mi < 4; mi++)
#pragma unroll
            for (int ni = 0; ni < 4; ni++) {
                int r0 = warpM * 64 + mi * 16 + (lane >> 2);
                int cn = warpN * 32 + ni * 8 + (lane & 3) * 2;
                float t0 = fmaf((float)d[mi][ni][0], scs[cn], shs[cn]);
                float t1 = fmaf((float)d[mi][ni][1], scs[cn + 1], shs[cn + 1]);
                *(uint16_t*)(stg + r0 * STG1_STR + cn) =
                    (uint16_t)(sgn8(t0) | (sgn8(t1) << 8));
                float t2 = fmaf((float)d[mi][ni][2], scs[cn], shs[cn]);
                float t3 = fmaf((float)d[mi][ni][3], scs[cn + 1], shs[cn + 1]);
                *(uint16_t*)(stg + (r0 + 8) * STG1_STR + cn) =
                    (uint16_t)(sgn8(t2) | (sgn8(t3) << 8));
            }
        __syncthreads();
#pragma unroll
        for (int k = 0; k < 4; k++) {
            int idx = tid + k * 256;
            int row = idx >> 3, q = idx & 7;
            int p = m0 + row;
            int w = p - (p / PW) * PW;
            if (p < MVALID && w < W) {
                uint4 v = *(const uint4*)(stg + row * STG1_STR + q * 16);
                *(uint4*)(g_act2 + ((size_t)n * PIX + p + PW + 1) * C + nhalf * 128 + q * 16) = v;
            }
        }
    } else {
        // BN + residual + clamp, per-warp transpose for coalesced NCHW stores
        float* stg = (float*)(sb + wid * STG2_WSTR);
#pragma unroll
        for (int hp = 0; hp < 2; hp++) {
#pragma unroll
            for (int mi = 0; mi < 4; mi++)
#pragma unroll
                for (int nj = 0; nj < 2; nj++) {
                    int ni = hp * 2 + nj;
                    int cl = nj * 8 + (lane & 3) * 2;                 // local col 0..15
                    int cn = warpN * 32 + hp * 16 + cl;               // 128-local co
                    int r0 = mi * 16 + (lane >> 2);
                    stg[cl * 68 + r0] = fmaf((float)d[mi][ni][0], scs[cn], shs[cn]);
                    stg[(cl + 1) * 68 + r0] = fmaf((float)d[mi][ni][1], scs[cn + 1], shs[cn + 1]);
                    stg[cl * 68 + r0 + 8] = fmaf((float)d[mi][ni][2], scs[cn], shs[cn]);
                    stg[(cl + 1) * 68 + r0 + 8] = fmaf((float)d[mi][ni][3], scs[cn + 1], shs[cn + 1]);
                }
            __syncwarp();
#pragma unroll
            for (int c = 0; c < 16; c++) {
                int co = nhalf * 128 + warpN * 32 + hp * 16 + c;
#pragma unroll
                for (int half = 0; half < 2; half++) {
                    int lp = lane + half * 32;
                    int p = m0 + warpM * 64 + lp;
                    int h = p / PW, w = p - h * PW;
                    if (p < MVALID && w < W) {
                        size_t oi = (((size_t)n * C + co) * H + h) * W + w;
                        float v = stg[c * 68 + lp] + xres[oi];
                        out[oi] = fminf(1.f, fmaxf(-1.f, v));
                    }
                }
            }
            __syncwarp();
        }
    }
}

extern "C" void kernel_launch(void* const* d_in, const int* in_sizes, int n_in,
                              void* d_out, int out_size) {
    (void)in_sizes; (void)n_in; (void)out_size;
    const float* x = (const float*)d_in[0];
    const float* w1 = (const float*)d_in[1];
    const float* g1 = (const float*)d_in[2];
    const float* b1 = (const float*)d_in[3];
    const float* m1 = (const float*)d_in[4];
    const float* v1 = (const float*)d_in[5];
    const float* w2 = (const float*)d_in[6];
    const float* g2 = (const float*)d_in[7];
    const float* b2 = (const float*)d_in[8];
    const float* m2 = (const float*)d_in[9];
    const float* v2 = (const float*)d_in[10];
    float* out = (float*)d_out;

    k_zero<<<2048, 256>>>();
    k_pack_x<<<dim3(H, Nn), 256>>>(x);
    k_pack_w<<<C, C>>>(w1, 0);
    k_pack_w<<<C, C>>>(w2, 1);

    dim3 grid(MTILES, NSPLIT, Nn);
    k_conv<1><<<grid, 256, DYN>>>(g1, b1, m1, v1, nullptr, nullptr);
    k_conv<2><<<grid, 256, DYN>>>(g2, b2, m2, v2, x, out);
}

// round 5
// speedup vs baseline: 2.3062x; 2.3062x over previous
#include <cuda_runtime.h>
#include <stdint.h>

#define BN_EPS 1e-5f

namespace {
constexpr int Nn = 64, C = 256, H = 56, W = 56;
constexpr int HP = H + 2, WPAD = W + 2;         // zero-padded bitplane dims
constexpr int WORDS = C / 32;                    // 8 words of channel bits
constexpr int KW = 9 * WORDS;                    // 72 (tap, word) pairs
constexpr int TH = 8;                            // output rows per block
constexpr int ROWSTR = 34;                       // smem row stride (words)
constexpr int PLANE = (TH + 2) * ROWSTR;         // 340 per channel-word plane
constexpr long long PIXWORDS = (long long)Nn * HP * WPAD * WORDS;
}

// Packed bitplanes (sign / nonzero) for stage inputs; padded borders stay nz=0.
__device__ uint32_t g_s1[Nn * HP * WPAD * WORDS];
__device__ uint32_t g_z1[Nn * HP * WPAD * WORDS];
__device__ uint32_t g_s2[Nn * HP * WPAD * WORDS];
__device__ uint32_t g_z2[Nn * HP * WPAD * WORDS];
__device__ uint32_t g_wb1[C * KW];
__device__ uint32_t g_wb2[C * KW];

// Full adder: 3 words -> sum (w) + carry (2w). Each output is one LOP3.
__device__ __forceinline__ void fa(uint32_t a, uint32_t b, uint32_t c,
                                   uint32_t& s, uint32_t& cy) {
    s = a ^ b ^ c;
    cy = (a & b) | (c & (a | b));
}

__global__ void k_zero_nz() {
    long long stride = (long long)gridDim.x * blockDim.x;
    for (long long i = blockIdx.x * (long long)blockDim.x + threadIdx.x;
         i < PIXWORDS; i += stride) {
        g_z1[i] = 0u;
        g_z2[i] = 0u;
    }
}

// Pack input activations: grid (H, N), block (W=56, WORDS=8).
__global__ void k_pack_x(const float* __restrict__ x) {
    const int h = blockIdx.x;
    const int n = blockIdx.y;
    const int w = threadIdx.x;
    const int wd = threadIdx.y;
    const float* xp = x + (((long long)n * C + wd * 32) * H + h) * W + w;
    uint32_t s = 0, z = 0;
#pragma unroll
    for (int ci = 0; ci < 32; ci++) {
        float v = xp[(long long)ci * (H * W)];
        s |= (v > 0.f ? 1u : 0u) << ci;
        z |= (v != 0.f ? 1u : 0u) << ci;
    }
    long long idx = (((long long)n * HP + (h + 1)) * WPAD + (w + 1)) * WORDS + wd;
    g_s1[idx] = s;
    g_z1[idx] = z;
}

// Pack weights: grid (C), block (WORDS=8, 9 taps).
__global__ void k_pack_w(const float* __restrict__ w, int which) {
    uint32_t* __restrict__ outw = which ? g_wb2 : g_wb1;
    const int co = blockIdx.x;
    const int wd = threadIdx.x;
    const int tap = threadIdx.y;
    uint32_t s = 0;
#pragma unroll
    for (int ci = 0; ci < 32; ci++) {
        float v = w[(((long long)co * C) + wd * 32 + ci) * 9 + tap];
        s |= (v > 0.f ? 1u : 0u) << ci;
    }
    outw[co * KW + tap * WORDS + wd] = s;
}

// Binary conv + BN (+ residual/clip or re-binarize), CSA-compressed popcount.
// Grid: (2 w-chunks, H/TH, N). Block: 256 threads = 8 warps.
// Warp lanes = output w; warp id = output channel word (32 co per warp).
template <int STAGE>
__global__ __launch_bounds__(256, 2) void k_bconv(
    const float* __restrict__ bn_g, const float* __restrict__ bn_b,
    const float* __restrict__ bn_m, const float* __restrict__ bn_v,
    const float* __restrict__ xres, float* __restrict__ out) {
    const uint32_t* __restrict__ sIn = (STAGE == 1) ? g_s1 : g_s2;
    const uint32_t* __restrict__ zIn = (STAGE == 1) ? g_z1 : g_z2;
    const uint32_t* __restrict__ wb = (STAGE == 1) ? g_wb1 : g_wb2;

    __shared__ uint32_t xs[WORDS * PLANE];
    __shared__ uint32_t xz[WORDS * PLANE];

    const int chunk = blockIdx.x;
    const int h0 = blockIdx.y * TH;
    const int n = blockIdx.z;
    const int tid = threadIdx.x;
    const int w0 = chunk * 32;

    // Load (TH+2) x 34 window of 8 sign/nz words, planar layout [wd][r][c].
    const int LW = WORDS * PLANE;
    for (int i = tid; i < LW; i += 256) {
        int wd = i & 7;
        int c = (i >> 3) % ROWSTR;
        int r = (i >> 3) / ROWSTR;
        int col = w0 + c;
        uint32_t s = 0, z = 0;
        if (col < WPAD) {
            long long gi = (((long long)n * HP + (h0 + r)) * WPAD + col) * WORDS + wd;
            s = sIn[gi];
            z = zIn[gi];
        }
        int si = wd * PLANE + r * ROWSTR + c;
        xs[si] = s;
        xz[si] = z;
    }
    __syncthreads();

    const int lane = tid & 31;
    const int wid = tid >> 5;
    const int ow = w0 + lane;
    const bool act = (ow < W);

    // base[r] = sum popc(nz) over the 72-word window (shared by all co), CSA'd.
    int base[TH];
#pragma unroll
    for (int r = 0; r < TH; r++) base[r] = 0;
    for (int g = 0; g < 8; g++) {
        int off[9];
#pragma unroll
        for (int q = 0; q < 9; q++) {
            int k = g * 9 + q;
            int wd = k & 7, tap = k >> 3;
            off[q] = wd * PLANE + (tap / 3) * ROWSTR + (tap % 3) + lane;
        }
#pragma unroll
        for (int r = 0; r < TH; r++) {
            uint32_t z0 = xz[off[0] + r * ROWSTR], z1 = xz[off[1] + r * ROWSTR];
            uint32_t z2 = xz[off[2] + r * ROWSTR], z3 = xz[off[3] + r * ROWSTR];
            uint32_t z4 = xz[off[4] + r * ROWSTR], z5 = xz[off[5] + r * ROWSTR];
            uint32_t z6 = xz[off[6] + r * ROWSTR], z7 = xz[off[7] + r * ROWSTR];
            uint32_t z8 = xz[off[8] + r * ROWSTR];
            uint32_t s0, c0, s1, c1, s2, c2, S, C2, S2, C4;
            fa(z0, z1, z2, s0, c0);
            fa(z3, z4, z5, s1, c1);
            fa(z6, z7, z8, s2, c2);
            fa(s0, s1, s2, S, C2);
            fa(c0, c1, c2, S2, C4);
            base[r] += __popc(S) + 2 * (__popc(C2) + __popc(S2)) + 4 * __popc(C4);
        }
    }

    uint32_t osig[TH], onz[TH];
    if (STAGE == 1) {
#pragma unroll
        for (int r = 0; r < TH; r++) {
            osig[r] = 0u;
            onz[r] = 0u;
        }
    }

    for (int j0 = 0; j0 < 32; j0 += 4) {
        int acc[4][TH];
#pragma unroll
        for (int jj = 0; jj < 4; jj++)
#pragma unroll
            for (int r = 0; r < TH; r++) acc[jj][r] = 0;

        const uint32_t* wp = wb + (wid * 32 + j0) * KW;
        for (int g = 0; g < 8; g++) {
            uint32_t wk[4][9];
#pragma unroll
            for (int c4 = 0; c4 < 4; c4++)
#pragma unroll
                for (int t = 0; t < 9; t++)
                    wk[c4][t] = __ldg(wp + c4 * KW + g * 9 + t);
            int off[9];
#pragma unroll
            for (int q = 0; q < 9; q++) {
                int k = g * 9 + q;
                int wd = k & 7, tap = k >> 3;
                off[q] = wd * PLANE + (tap / 3) * ROWSTR + (tap % 3) + lane;
            }
#pragma unroll
            for (int r = 0; r < TH; r++) {
                uint32_t sA[4][3], cA[4][3];
#pragma unroll
                for (int t3 = 0; t3 < 3; t3++) {
                    uint32_t sx0 = xs[off[t3 * 3 + 0] + r * ROWSTR];
                    uint32_t zx0 = xz[off[t3 * 3 + 0] + r * ROWSTR];
                    uint32_t sx1 = xs[off[t3 * 3 + 1] + r * ROWSTR];
                    uint32_t zx1 = xz[off[t3 * 3 + 1] + r * ROWSTR];
                    uint32_t sx2 = xs[off[t3 * 3 + 2] + r * ROWSTR];
                    uint32_t zx2 = xz[off[t3 * 3 + 2] + r * ROWSTR];
#pragma unroll
                    for (int c4 = 0; c4 < 4; c4++) {
                        uint32_t m0 = zx0 & (sx0 ^ wk[c4][t3 * 3 + 0]);
                        uint32_t m1 = zx1 & (sx1 ^ wk[c4][t3 * 3 + 1]);
                        uint32_t m2 = zx2 & (sx2 ^ wk[c4][t3 * 3 + 2]);
                        fa(m0, m1, m2, sA[c4][t3], cA[c4][t3]);
                    }
                }
#pragma unroll
                for (int c4 = 0; c4 < 4; c4++) {
                    uint32_t S, C2, S2, C4w;
                    fa(sA[c4][0], sA[c4][1], sA[c4][2], S, C2);
                    fa(cA[c4][0], cA[c4][1], cA[c4][2], S2, C4w);
                    acc[c4][r] += __popc(S) + 2 * (__popc(C2) + __popc(S2)) +
                                  4 * __popc(C4w);
                }
            }
        }

#pragma unroll
        for (int jj = 0; jj < 4; jj++) {
            const int co = wid * 32 + j0 + jj;
            const float sc = bn_g[co] * rsqrtf(bn_v[co] + BN_EPS);
            const float sh = bn_b[co] - bn_m[co] * sc;
#pragma unroll
            for (int r = 0; r < TH; r++) {
                float t = fmaf((float)(base[r] - 2 * acc[jj][r]), sc, sh);
                if (STAGE == 1) {
                    osig[r] |= (t > 0.f ? 1u : 0u) << (j0 + jj);
                    onz[r] |= (t != 0.f ? 1u : 0u) << (j0 + jj);
                } else {
                    if (act) {
                        long long oi =
                            (((long long)n * C + co) * H + (h0 + r)) * W + ow;
                        float v = t + xres[oi];
                        v = fminf(1.f, fmaxf(-1.f, v));
                        out[oi] = v;
                    }
                }
            }
        }
    }

    if (STAGE == 1 && act) {
#pragma unroll
        for (int r = 0; r < TH; r++) {
            long long gi =
                (((long long)n * HP + (h0 + r + 1)) * WPAD + (ow + 1)) * WORDS + wid;
            g_s2[gi] = osig[r];
            g_z2[gi] = onz[r];
        }
    }
}

extern "C" void kernel_launch(void* const* d_in, const int* in_sizes, int n_in,
                              void* d_out, int out_size) {
    (void)in_sizes;
    (void)n_in;
    (void)out_size;
    const float* x = (const float*)d_in[0];
    const float* w1 = (const float*)d_in[1];
    const float* g1 = (const float*)d_in[2];
    const float* b1 = (const float*)d_in[3];
    const float* m1 = (const float*)d_in[4];
    const float* v1 = (const float*)d_in[5];
    const float* w2 = (const float*)d_in[6];
    const float* g2 = (const float*)d_in[7];
    const float* b2 = (const float*)d_in[8];
    const float* m2 = (const float*)d_in[9];
    const float* v2 = (const float*)d_in[10];
    float* out = (float*)d_out;

    k_zero_nz<<<1024, 256>>>();
    k_pack_x<<<dim3(H, Nn), dim3(W, WORDS)>>>(x);
    k_pack_w<<<C, dim3(WORDS, 9)>>>(w1, 0);
    k_pack_w<<<C, dim3(WORDS, 9)>>>(w2, 1);

    dim3 grid(2, H / TH, Nn);
    k_bconv<1><<<grid, 256>>>(g1, b1, m1, v1, x, out);
    k_bconv<2><<<grid, 256>>>(g2, b2, m2, v2, x, out);
}